// round 1
// baseline (speedup 1.0000x reference)
#include <cuda_runtime.h>
#include <cstdint>

// DiscriminativeReconstructionLoss — Otsu threshold via 2-level histogram.
// Level-1: 8192 bins over fixed [-16, 16) (clamped; consistent bin fn across passes).
// Level-2: 8192 bins over a 10-bin window around the level-1 best boundary.
// Objective uses only prefix count & sum (sum-of-squares cancels):
//   f(i) = T2 - [S1^2/i + (T-S1)^2/(K-i)]

#define NB 8192
#define NT_HIST 512
#define NBLK_HIST 296

__device__ unsigned int       d_cnt1[NB];
__device__ double             d_sum1[NB];
__device__ unsigned int       d_cnt2[NB];
__device__ double             d_sum2[NB];
__device__ double             d_T;
__device__ double             d_T2;
__device__ unsigned long long d_K;
__device__ int                d_lob, d_hib;
__device__ double             d_lo, d_sc2;
__device__ unsigned long long d_Cb;
__device__ double             d_Sb;

__global__ void k_init() {
    int i = blockIdx.x * blockDim.x + threadIdx.x;
    if (i < NB) { d_cnt1[i] = 0u; d_sum1[i] = 0.0; d_cnt2[i] = 0u; d_sum2[i] = 0.0; }
    if (i == 0) { d_T = 0.0; d_T2 = 0.0; d_K = 0ull; }
}

__device__ __forceinline__ int bin1_of(float v) {
    int b = (int)((v + 16.0f) * 256.0f);   // 8192 bins over [-16,16)
    return min(max(b, 0), NB - 1);
}

__global__ void k_hist1(const float* __restrict__ x, const unsigned char* __restrict__ msk, int n4) {
    extern __shared__ unsigned char smem[];
    unsigned int* scnt = (unsigned int*)smem;
    float*        ssum = (float*)(smem + NB * sizeof(unsigned int));
    for (int b = threadIdx.x; b < NB; b += blockDim.x) { scnt[b] = 0u; ssum[b] = 0.0f; }
    __syncthreads();

    unsigned int lK = 0; double lT = 0.0, lT2 = 0.0;
    int stride = gridDim.x * blockDim.x;
    const float4* x4 = (const float4*)x;
    const uchar4* m4 = (const uchar4*)msk;
    for (int i = blockIdx.x * blockDim.x + threadIdx.x; i < n4; i += stride) {
        float4 v = x4[i];
        uchar4 mm = m4[i];
        float vv[4] = {v.x, v.y, v.z, v.w};
        unsigned char mb[4] = {mm.x, mm.y, mm.z, mm.w};
        #pragma unroll
        for (int j = 0; j < 4; j++) {
            if (mb[j]) {
                float f = vv[j];
                int b = bin1_of(f);
                atomicAdd(&scnt[b], 1u);
                atomicAdd(&ssum[b], f);
                lK++;
                lT  += (double)f;
                lT2 += (double)f * (double)f;
            }
        }
    }
    // warp-reduce K, T, T2 then global f64 atomics
    for (int o = 16; o; o >>= 1) {
        lK  += __shfl_down_sync(0xffffffffu, lK, o);
        lT  += __shfl_down_sync(0xffffffffu, lT, o);
        lT2 += __shfl_down_sync(0xffffffffu, lT2, o);
    }
    if ((threadIdx.x & 31) == 0) {
        atomicAdd(&d_K, (unsigned long long)lK);
        atomicAdd(&d_T, lT);
        atomicAdd(&d_T2, lT2);
    }
    __syncthreads();
    for (int b = threadIdx.x; b < NB; b += blockDim.x) {
        unsigned int c = scnt[b];
        if (c) { atomicAdd(&d_cnt1[b], c); atomicAdd(&d_sum1[b], (double)ssum[b]); }
    }
}

__global__ void k_pick() {
    __shared__ unsigned long long pc[1024];
    __shared__ double             ps[1024];
    __shared__ double             bg[1024];
    __shared__ int                bi[1024];
    int t = threadIdx.x;
    unsigned long long c = 0; double s = 0.0;
    #pragma unroll
    for (int j = 0; j < 8; j++) { int b = t * 8 + j; c += d_cnt1[b]; s += d_sum1[b]; }
    pc[t] = c; ps[t] = s;
    __syncthreads();
    for (int o = 1; o < 1024; o <<= 1) {        // Hillis-Steele inclusive scan
        unsigned long long cc = 0; double ss = 0.0;
        if (t >= o) { cc = pc[t - o]; ss = ps[t - o]; }
        __syncthreads();
        if (t >= o) { pc[t] += cc; ps[t] += ss; }
        __syncthreads();
    }
    unsigned long long cexcl = t ? pc[t - 1] : 0ull;
    double             sexcl = t ? ps[t - 1] : 0.0;

    double T = d_T; unsigned long long Ku = d_K; double K = (double)Ku;
    double bestg = -1e300; int besti = 0x7fffffff;
    unsigned long long ci = cexcl; double si = sexcl;
    #pragma unroll
    for (int j = 0; j < 8; j++) {
        int b = t * 8 + j;
        ci += d_cnt1[b]; si += d_sum1[b];
        if (ci > 0ull && ci < Ku) {
            double di = (double)ci;
            double r = T - si;
            double gg = si * si / di + r * r / (K - di);
            if (gg > bestg) { bestg = gg; besti = b; }
        }
    }
    bg[t] = bestg; bi[t] = besti;
    __syncthreads();
    for (int o = 512; o; o >>= 1) {
        if (t < o) {
            if (bg[t + o] > bg[t] || (bg[t + o] == bg[t] && bi[t + o] < bi[t])) {
                bg[t] = bg[t + o]; bi[t] = bi[t + o];
            }
        }
        __syncthreads();
    }
    if (t == 0) {
        int bs = bi[0];
        int lob = bs - 4; if (lob < 0) lob = 0;
        int hib = bs + 5; if (hib > NB - 1) hib = NB - 1;
        d_lob = lob; d_hib = hib;
        double w  = 32.0 / (double)NB;
        double lo = -16.0 + (double)lob * w;
        d_lo  = lo;
        d_sc2 = (double)NB / ((double)(hib - lob + 1) * w);
        // exact prefix (count,sum) of all values strictly below the window
        unsigned long long Cb = 0ull; double Sb = 0.0;
        if (lob > 0) {
            int last = lob - 1; int tt = last / 8;
            if (tt > 0) { Cb = pc[tt - 1]; Sb = ps[tt - 1]; }
            for (int b = tt * 8; b <= last; b++) { Cb += d_cnt1[b]; Sb += d_sum1[b]; }
        }
        d_Cb = Cb; d_Sb = Sb;
    }
}

__global__ void k_hist2(const float* __restrict__ x, const unsigned char* __restrict__ msk, int n4) {
    extern __shared__ unsigned char smem[];
    unsigned int* scnt = (unsigned int*)smem;
    float*        ssum = (float*)(smem + NB * sizeof(unsigned int));
    for (int b = threadIdx.x; b < NB; b += blockDim.x) { scnt[b] = 0u; ssum[b] = 0.0f; }
    __syncthreads();

    int lob = d_lob, hib = d_hib;
    float lo = (float)d_lo;
    float sc = (float)d_sc2;
    int stride = gridDim.x * blockDim.x;
    const float4* x4 = (const float4*)x;
    const uchar4* m4 = (const uchar4*)msk;
    for (int i = blockIdx.x * blockDim.x + threadIdx.x; i < n4; i += stride) {
        float4 v = x4[i];
        uchar4 mm = m4[i];
        float vv[4] = {v.x, v.y, v.z, v.w};
        unsigned char mb[4] = {mm.x, mm.y, mm.z, mm.w};
        #pragma unroll
        for (int j = 0; j < 4; j++) {
            if (mb[j]) {
                float f = vv[j];
                int b1 = bin1_of(f);               // identical bin fn => exact membership
                if (b1 >= lob && b1 <= hib) {
                    int b2 = (int)((f - lo) * sc);
                    b2 = min(max(b2, 0), NB - 1);
                    atomicAdd(&scnt[b2], 1u);
                    atomicAdd(&ssum[b2], f);
                }
            }
        }
    }
    __syncthreads();
    for (int b = threadIdx.x; b < NB; b += blockDim.x) {
        unsigned int c = scnt[b];
        if (c) { atomicAdd(&d_cnt2[b], c); atomicAdd(&d_sum2[b], (double)ssum[b]); }
    }
}

__global__ void k_final(float* __restrict__ out) {
    __shared__ unsigned long long pc[1024];
    __shared__ double             ps[1024];
    __shared__ double             bg[1024];
    __shared__ int                bi[1024];
    int t = threadIdx.x;
    unsigned long long c = 0; double s = 0.0;
    #pragma unroll
    for (int j = 0; j < 8; j++) { int b = t * 8 + j; c += d_cnt2[b]; s += d_sum2[b]; }
    pc[t] = c; ps[t] = s;
    __syncthreads();
    for (int o = 1; o < 1024; o <<= 1) {
        unsigned long long cc = 0; double ss = 0.0;
        if (t >= o) { cc = pc[t - o]; ss = ps[t - o]; }
        __syncthreads();
        if (t >= o) { pc[t] += cc; ps[t] += ss; }
        __syncthreads();
    }
    unsigned long long cexcl = (t ? pc[t - 1] : 0ull) + d_Cb;
    double             sexcl = (t ? ps[t - 1] : 0.0) + d_Sb;

    double T = d_T, T2 = d_T2; unsigned long long Ku = d_K; double K = (double)Ku;
    double bestg = -1e300; int besti = 0x7fffffff;
    unsigned long long ci = cexcl; double si = sexcl;
    #pragma unroll
    for (int j = 0; j < 8; j++) {
        int b = t * 8 + j;
        ci += d_cnt2[b]; si += d_sum2[b];
        if (ci > 0ull && ci < Ku) {
            double di = (double)ci;
            double r = T - si;
            double gg = si * si / di + r * r / (K - di);
            if (gg > bestg) { bestg = gg; besti = b; }
        }
    }
    bg[t] = bestg; bi[t] = besti;
    __syncthreads();
    for (int o = 512; o; o >>= 1) {
        if (t < o) {
            if (bg[t + o] > bg[t] || (bg[t + o] == bg[t] && bi[t + o] < bi[t])) {
                bg[t] = bg[t + o]; bi[t] = bi[t + o];
            }
        }
        __syncthreads();
    }
    if (t == 0) {
        int bs = bi[0];
        int tt = bs / 8;
        unsigned long long Ci = d_Cb + (tt ? pc[tt - 1] : 0ull);
        double             Si = d_Sb + (tt ? ps[tt - 1] : 0.0);
        for (int b = tt * 8; b <= bs; b++) { Ci += d_cnt2[b]; Si += d_sum2[b]; }
        double di = (double)Ci;
        double r  = T - Si;
        double gmax    = Si * Si / di + r * r / (K - di);
        double regmin  = T2 - gmax;
        double var_tot = (T2 - T * T / K) / K;
        double reg     = regmin / var_tot / K;
        double pos_mean = Si / di;
        out[0] = (float)(pos_mean + 0.5 * reg);
    }
}

extern "C" void kernel_launch(void* const* d_in, const int* in_sizes, int n_in,
                              void* d_out, int out_size) {
    const float*         x = (const float*)d_in[0];
    const unsigned char* m = (const unsigned char*)d_in[1];
    int n  = in_sizes[0];
    int n4 = n >> 2;

    cudaFuncSetAttribute(k_hist1, cudaFuncAttributeMaxDynamicSharedMemorySize, 65536);
    cudaFuncSetAttribute(k_hist2, cudaFuncAttributeMaxDynamicSharedMemorySize, 65536);

    k_init<<<(NB + 255) / 256, 256>>>();
    k_hist1<<<NBLK_HIST, NT_HIST, 65536>>>(x, m, n4);
    k_pick<<<1, 1024>>>();
    k_hist2<<<NBLK_HIST, NT_HIST, 65536>>>(x, m, n4);
    k_final<<<1, 1024>>>((float*)d_out);
}

// round 2
// speedup vs baseline: 1.3990x; 1.3990x over previous
#include <cuda_runtime.h>
#include <cstdint>

// DiscriminativeReconstructionLoss — Otsu threshold via 2-level histogram.
// Level-1: 4096 bins over fixed [-16, 16) (clamped; identical bin fn both passes).
// Level-2: 4096 bins over a ~10-bin window around the level-1 best boundary.
// Objective uses only prefix count & sum (sum-of-squares cancels):
//   f(i) = T2 - [S1^2/i + (T-S1)^2/(K-i)]   -> maximize g(i) = S1^2/i + (T-S1)^2/(K-i)

#define NB 4096
#define NT_HIST 512
#define NBLK_HIST 608   // 4 blocks x 152 SMs

__device__ unsigned int       d_cnt1[NB];
__device__ double             d_sum1[NB];
__device__ unsigned int       d_cnt2[NB];
__device__ double             d_sum2[NB];
__device__ double             d_T;
__device__ double             d_T2;
__device__ unsigned long long d_K;
__device__ int                d_lob, d_hib;
__device__ float              d_lo, d_sc2;
__device__ unsigned long long d_Cb;
__device__ double             d_Sb;

__global__ void k_init() {
    int i = blockIdx.x * blockDim.x + threadIdx.x;
    if (i < NB) { d_cnt1[i] = 0u; d_sum1[i] = 0.0; d_cnt2[i] = 0u; d_sum2[i] = 0.0; }
    if (i == 0) { d_T = 0.0; d_T2 = 0.0; d_K = 0ull; }
}

__device__ __forceinline__ int bin1_of(float v) {
    int b = (int)((v + 16.0f) * 128.0f);   // 4096 bins over [-16,16)
    return min(max(b, 0), NB - 1);
}

__global__ void __launch_bounds__(NT_HIST, 4)
k_hist1(const float* __restrict__ x, const unsigned int* __restrict__ msk, int n4) {
    __shared__ unsigned int scnt[NB];
    __shared__ float        ssum[NB];
    for (int b = threadIdx.x; b < NB; b += blockDim.x) { scnt[b] = 0u; ssum[b] = 0.0f; }
    __syncthreads();

    unsigned int lK = 0; double lT = 0.0, lT2 = 0.0;
    const int stride = gridDim.x * blockDim.x;
    const float4* x4 = (const float4*)x;
    int i = blockIdx.x * blockDim.x + threadIdx.x;

    for (; i + stride < n4; i += 2 * stride) {
        float4 va = __ldcs(&x4[i]);
        unsigned int ma = __ldcs(&msk[i]);
        float4 vb = __ldcs(&x4[i + stride]);
        unsigned int mb = __ldcs(&msk[i + stride]);
        float vva[4] = {va.x, va.y, va.z, va.w};
        float vvb[4] = {vb.x, vb.y, vb.z, vb.w};
        #pragma unroll
        for (int j = 0; j < 4; j++) {
            if ((ma >> (8 * j)) & 0xff) {
                float f = vva[j];
                int b = bin1_of(f);
                atomicAdd(&scnt[b], 1u);
                atomicAdd(&ssum[b], f);
                lK++; lT += (double)f; lT2 = fma((double)f, (double)f, lT2);
            }
        }
        #pragma unroll
        for (int j = 0; j < 4; j++) {
            if ((mb >> (8 * j)) & 0xff) {
                float f = vvb[j];
                int b = bin1_of(f);
                atomicAdd(&scnt[b], 1u);
                atomicAdd(&ssum[b], f);
                lK++; lT += (double)f; lT2 = fma((double)f, (double)f, lT2);
            }
        }
    }
    for (; i < n4; i += stride) {
        float4 va = __ldcs(&x4[i]);
        unsigned int ma = __ldcs(&msk[i]);
        float vva[4] = {va.x, va.y, va.z, va.w};
        #pragma unroll
        for (int j = 0; j < 4; j++) {
            if ((ma >> (8 * j)) & 0xff) {
                float f = vva[j];
                int b = bin1_of(f);
                atomicAdd(&scnt[b], 1u);
                atomicAdd(&ssum[b], f);
                lK++; lT += (double)f; lT2 = fma((double)f, (double)f, lT2);
            }
        }
    }

    for (int o = 16; o; o >>= 1) {
        lK  += __shfl_down_sync(0xffffffffu, lK, o);
        lT  += __shfl_down_sync(0xffffffffu, lT, o);
        lT2 += __shfl_down_sync(0xffffffffu, lT2, o);
    }
    if ((threadIdx.x & 31) == 0) {
        atomicAdd(&d_K, (unsigned long long)lK);
        atomicAdd(&d_T, lT);
        atomicAdd(&d_T2, lT2);
    }
    __syncthreads();
    for (int b = threadIdx.x; b < NB; b += blockDim.x) {
        unsigned int c = scnt[b];
        if (c) { atomicAdd(&d_cnt1[b], c); atomicAdd(&d_sum1[b], (double)ssum[b]); }
    }
}

__global__ void k_pick() {
    __shared__ unsigned long long pc[1024];
    __shared__ double             ps[1024];
    __shared__ double             bg[1024];
    __shared__ int                bi[1024];
    int t = threadIdx.x;
    unsigned long long c = 0; double s = 0.0;
    #pragma unroll
    for (int j = 0; j < 4; j++) { int b = t * 4 + j; c += d_cnt1[b]; s += d_sum1[b]; }
    pc[t] = c; ps[t] = s;
    __syncthreads();
    for (int o = 1; o < 1024; o <<= 1) {        // Hillis-Steele inclusive scan
        unsigned long long cc = 0; double ss = 0.0;
        if (t >= o) { cc = pc[t - o]; ss = ps[t - o]; }
        __syncthreads();
        if (t >= o) { pc[t] += cc; ps[t] += ss; }
        __syncthreads();
    }
    unsigned long long cexcl = t ? pc[t - 1] : 0ull;
    double             sexcl = t ? ps[t - 1] : 0.0;

    double T = d_T; unsigned long long Ku = d_K; double K = (double)Ku;
    double bestg = -1e300; int besti = 0x7fffffff;
    unsigned long long ci = cexcl; double si = sexcl;
    #pragma unroll
    for (int j = 0; j < 4; j++) {
        int b = t * 4 + j;
        ci += d_cnt1[b]; si += d_sum1[b];
        if (ci > 0ull && ci < Ku) {
            double di = (double)ci;
            double r = T - si;
            double gg = si * si / di + r * r / (K - di);
            if (gg > bestg) { bestg = gg; besti = b; }
        }
    }
    bg[t] = bestg; bi[t] = besti;
    __syncthreads();
    for (int o = 512; o; o >>= 1) {
        if (t < o) {
            if (bg[t + o] > bg[t] || (bg[t + o] == bg[t] && bi[t + o] < bi[t])) {
                bg[t] = bg[t + o]; bi[t] = bi[t + o];
            }
        }
        __syncthreads();
    }
    if (t == 0) {
        int bs = bi[0];
        int lob = bs - 4; if (lob < 0) lob = 0;
        int hib = bs + 5; if (hib > NB - 1) hib = NB - 1;
        d_lob = lob; d_hib = hib;
        double w  = 32.0 / (double)NB;
        double lo = -16.0 + (double)lob * w;
        d_lo  = (float)lo;
        d_sc2 = (float)((double)NB / ((double)(hib - lob + 1) * w));
        // exact prefix (count,sum) of all values strictly below the window
        unsigned long long Cb = 0ull; double Sb = 0.0;
        if (lob > 0) {
            int last = lob - 1; int tt = last / 4;
            if (tt > 0) { Cb = pc[tt - 1]; Sb = ps[tt - 1]; }
            for (int b = tt * 4; b <= last; b++) { Cb += d_cnt1[b]; Sb += d_sum1[b]; }
        }
        d_Cb = Cb; d_Sb = Sb;
    }
}

__global__ void __launch_bounds__(NT_HIST, 4)
k_hist2(const float* __restrict__ x, const unsigned int* __restrict__ msk, int n4) {
    __shared__ unsigned int scnt[NB];
    __shared__ float        ssum[NB];
    for (int b = threadIdx.x; b < NB; b += blockDim.x) { scnt[b] = 0u; ssum[b] = 0.0f; }
    __syncthreads();

    const int lob = d_lob, hib = d_hib;
    const float lo = d_lo;
    const float sc = d_sc2;
    const int stride = gridDim.x * blockDim.x;
    const float4* x4 = (const float4*)x;
    int i = blockIdx.x * blockDim.x + threadIdx.x;

    for (; i + stride < n4; i += 2 * stride) {
        float4 va = __ldcs(&x4[i]);
        unsigned int ma = __ldcs(&msk[i]);
        float4 vb = __ldcs(&x4[i + stride]);
        unsigned int mb = __ldcs(&msk[i + stride]);
        float vva[4] = {va.x, va.y, va.z, va.w};
        float vvb[4] = {vb.x, vb.y, vb.z, vb.w};
        #pragma unroll
        for (int j = 0; j < 4; j++) {
            if ((ma >> (8 * j)) & 0xff) {
                float f = vva[j];
                int b1 = bin1_of(f);               // identical bin fn => exact membership
                if (b1 >= lob && b1 <= hib) {
                    int b2 = min(max((int)((f - lo) * sc), 0), NB - 1);
                    atomicAdd(&scnt[b2], 1u);
                    atomicAdd(&ssum[b2], f);
                }
            }
        }
        #pragma unroll
        for (int j = 0; j < 4; j++) {
            if ((mb >> (8 * j)) & 0xff) {
                float f = vvb[j];
                int b1 = bin1_of(f);
                if (b1 >= lob && b1 <= hib) {
                    int b2 = min(max((int)((f - lo) * sc), 0), NB - 1);
                    atomicAdd(&scnt[b2], 1u);
                    atomicAdd(&ssum[b2], f);
                }
            }
        }
    }
    for (; i < n4; i += stride) {
        float4 va = __ldcs(&x4[i]);
        unsigned int ma = __ldcs(&msk[i]);
        float vva[4] = {va.x, va.y, va.z, va.w};
        #pragma unroll
        for (int j = 0; j < 4; j++) {
            if ((ma >> (8 * j)) & 0xff) {
                float f = vva[j];
                int b1 = bin1_of(f);
                if (b1 >= lob && b1 <= hib) {
                    int b2 = min(max((int)((f - lo) * sc), 0), NB - 1);
                    atomicAdd(&scnt[b2], 1u);
                    atomicAdd(&ssum[b2], f);
                }
            }
        }
    }
    __syncthreads();
    for (int b = threadIdx.x; b < NB; b += blockDim.x) {
        unsigned int c = scnt[b];
        if (c) { atomicAdd(&d_cnt2[b], c); atomicAdd(&d_sum2[b], (double)ssum[b]); }
    }
}

__global__ void k_final(float* __restrict__ out) {
    __shared__ unsigned long long pc[1024];
    __shared__ double             ps[1024];
    __shared__ double             bg[1024];
    __shared__ int                bi[1024];
    int t = threadIdx.x;
    unsigned long long c = 0; double s = 0.0;
    #pragma unroll
    for (int j = 0; j < 4; j++) { int b = t * 4 + j; c += d_cnt2[b]; s += d_sum2[b]; }
    pc[t] = c; ps[t] = s;
    __syncthreads();
    for (int o = 1; o < 1024; o <<= 1) {
        unsigned long long cc = 0; double ss = 0.0;
        if (t >= o) { cc = pc[t - o]; ss = ps[t - o]; }
        __syncthreads();
        if (t >= o) { pc[t] += cc; ps[t] += ss; }
        __syncthreads();
    }
    unsigned long long cexcl = (t ? pc[t - 1] : 0ull) + d_Cb;
    double             sexcl = (t ? ps[t - 1] : 0.0) + d_Sb;

    double T = d_T, T2 = d_T2; unsigned long long Ku = d_K; double K = (double)Ku;
    double bestg = -1e300; int besti = 0x7fffffff;
    unsigned long long ci = cexcl; double si = sexcl;
    #pragma unroll
    for (int j = 0; j < 4; j++) {
        int b = t * 4 + j;
        ci += d_cnt2[b]; si += d_sum2[b];
        if (ci > 0ull && ci < Ku) {
            double di = (double)ci;
            double r = T - si;
            double gg = si * si / di + r * r / (K - di);
            if (gg > bestg) { bestg = gg; besti = b; }
        }
    }
    bg[t] = bestg; bi[t] = besti;
    __syncthreads();
    for (int o = 512; o; o >>= 1) {
        if (t < o) {
            if (bg[t + o] > bg[t] || (bg[t + o] == bg[t] && bi[t + o] < bi[t])) {
                bg[t] = bg[t + o]; bi[t] = bi[t + o];
            }
        }
        __syncthreads();
    }
    if (t == 0) {
        int bs = bi[0];
        int tt = bs / 4;
        unsigned long long Ci = d_Cb + (tt ? pc[tt - 1] : 0ull);
        double             Si = d_Sb + (tt ? ps[tt - 1] : 0.0);
        for (int b = tt * 4; b <= bs; b++) { Ci += d_cnt2[b]; Si += d_sum2[b]; }
        double di = (double)Ci;
        double r  = T - Si;
        double gmax    = Si * Si / di + r * r / (K - di);
        double regmin  = T2 - gmax;
        double var_tot = (T2 - T * T / K) / K;
        double reg     = regmin / var_tot / K;
        double pos_mean = Si / di;
        out[0] = (float)(pos_mean + 0.5 * reg);
    }
}

extern "C" void kernel_launch(void* const* d_in, const int* in_sizes, int n_in,
                              void* d_out, int out_size) {
    const float*        x = (const float*)d_in[0];
    const unsigned int* m = (const unsigned int*)d_in[1];
    int n  = in_sizes[0];
    int n4 = n >> 2;

    k_init<<<(NB + 255) / 256, 256>>>();
    k_hist1<<<NBLK_HIST, NT_HIST>>>(x, m, n4);
    k_pick<<<1, 1024>>>();
    k_hist2<<<NBLK_HIST, NT_HIST>>>(x, m, n4);
    k_final<<<1, 1024>>>((float*)d_out);
}